// round 4
// baseline (speedup 1.0000x reference)
#include <cuda_runtime.h>
#include <math.h>

namespace {
constexpr int Himg = 512, Wimg = 512, Bimg = 32;
constexpr int TILE_W = 64, TILE_H = 32, ROWS = 8;
constexpr int SWID = TILE_W + 2;   // 66
constexpr int SHGT = TILE_H + 2;   // 34
constexpr int NBLOCKS = (Wimg / TILE_W) * (Himg / TILE_H) * Bimg;  // 4096
}

typedef unsigned long long u64;

// 11 accumulators: [0]=mask sum, [1..4]=inp S1..S4, [5..8]=out S1..S8, [9]=tex, [10]=shape
__device__ double g_acc[11];
__device__ unsigned int g_count;

// ---- packed f32x2 helpers (SASS FFMA2/FADD2/FMUL2, sm_100+) ----
__device__ __forceinline__ u64 pk2(float lo, float hi) {
    u64 r; asm("mov.b64 %0,{%1,%2};" : "=l"(r) : "f"(lo), "f"(hi)); return r;
}
__device__ __forceinline__ void up2(u64 v, float& lo, float& hi) {
    asm("mov.b64 {%0,%1},%2;" : "=f"(lo), "=f"(hi) : "l"(v));
}
__device__ __forceinline__ u64 add2(u64 a, u64 b) {
    u64 r; asm("add.rn.f32x2 %0,%1,%2;" : "=l"(r) : "l"(a), "l"(b)); return r;
}
__device__ __forceinline__ u64 mul2(u64 a, u64 b) {
    u64 r; asm("mul.rn.f32x2 %0,%1,%2;" : "=l"(r) : "l"(a), "l"(b)); return r;
}
__device__ __forceinline__ u64 fma2(u64 a, u64 b, u64 c) {
    u64 r; asm("fma.rn.f32x2 %0,%1,%2,%3;" : "=l"(r) : "l"(a), "l"(b), "l"(c)); return r;
}

#define WRED(v)                                      \
    v += __shfl_xor_sync(0xffffffffu, v, 16);        \
    v += __shfl_xor_sync(0xffffffffu, v, 8);         \
    v += __shfl_xor_sync(0xffffffffu, v, 4);         \
    v += __shfl_xor_sync(0xffffffffu, v, 2);         \
    v += __shfl_xor_sync(0xffffffffu, v, 1);

__global__ __launch_bounds__(256) void loss_kernel(
    const float* __restrict__ inp, const float* __restrict__ outp,
    const float* __restrict__ mask, float* __restrict__ out) {
    __shared__ u64 sp[SHGT * SWID];           // packed (inp, out)
    __shared__ double red[8][11];
    __shared__ int last_flag;

    const int tx = threadIdx.x;               // 0..63
    const int ty = threadIdx.y;               // 0..3
    const int tid = ty * TILE_W + tx;
    const int img = blockIdx.z;
    const int x0 = blockIdx.x * TILE_W;
    const int y0 = blockIdx.y * TILE_H;
    const size_t ibase = (size_t)img * (size_t)(Himg * Wimg);

    // ---- halo load, no integer division ----
    const int gx_main = x0 + tx - 1;
    const bool okx_main = (gx_main >= 0) && (gx_main < Wimg);
    const int gx_ext = x0 + 64 + tx - 1;      // tx<2 only: cols 64,65
    const bool okx_ext = (gx_ext < Wimg);     // >=0 always
#pragma unroll
    for (int r = ty; r < SHGT; r += 4) {
        int gy = y0 + r - 1;
        bool oky = (gy >= 0) && (gy < Himg);
        float vi = 0.f, vo = 0.f;
        if (oky && okx_main) {
            size_t off = ibase + (size_t)gy * Wimg + (size_t)gx_main;
            vi = inp[off]; vo = outp[off];
        }
        sp[r * SWID + tx] = pk2(vi, vo);
        if (tx < 2) {
            float wi = 0.f, wo = 0.f;
            if (oky && okx_ext) {
                size_t off = ibase + (size_t)gy * Wimg + (size_t)gx_ext;
                wi = inp[off]; wo = outp[off];
            }
            sp[r * SWID + 64 + tx] = pk2(wi, wo);
        }
    }
    __syncthreads();

    const int rbase = ty * ROWS;
    const u64 C9   = pk2(1.f / 9.f, 1.f / 9.f);
    const u64 NEG4 = pk2(-4.f, -4.f);
    const u64 NEG1 = pk2(-1.f, -1.f);

    // ---- prime rolling window ----
    const u64* p0 = sp + rbase * SWID + tx;
    u64 L = p0[0], M = p0[1], R = p0[2];
    u64 rs0 = add2(add2(L, M), R);
    u64 rq0 = fma2(L, L, fma2(M, M, mul2(R, R)));
    u64 M0 = M;
    const u64* p1 = p0 + SWID;
    u64 L1 = p1[0], M1 = p1[1], R1 = p1[2];
    u64 rs1 = add2(add2(L1, M1), R1);
    u64 rq1 = fma2(L1, L1, fma2(M1, M1, mul2(R1, R1)));

    // accumulators
    float a0 = 0.f, atex = 0.f, ashp = 0.f;
    u64 acc1 = 0ull, acc2 = 0ull, acc3 = 0ull, acc4 = 0ull;  // packed (inp, out)

    const float* mrow = mask + ibase + (size_t)(y0 + rbase) * Wimg + (size_t)(x0 + tx);

#pragma unroll
    for (int k = 0; k < ROWS; k++) {
        const u64* p2 = p0 + (k + 2) * SWID;
        u64 L2 = p2[0], M2 = p2[1], R2 = p2[2];
        u64 rs2 = add2(add2(L2, M2), R2);
        u64 rq2 = fma2(L2, L2, fma2(M2, M2, mul2(R2, R2)));

        u64 s1 = add2(add2(rs0, rs1), rs2);
        u64 s2 = add2(add2(rq0, rq1), rq2);
        u64 lap = fma2(M1, NEG4, add2(add2(M0, M2), add2(L1, R1)));
        u64 mean = mul2(s1, C9);
        u64 t = mul2(mean, mean);
        u64 lv = fma2(t, NEG1, mul2(s2, C9));   // E[x^2] - E[x]^2

        float mk = mrow[k * Wimg];
        u64 mk2 = pk2(mk, mk);
        u64 cm = M1;
        u64 u = mul2(cm, mk2); acc1 = add2(acc1, u);
        u = mul2(u, cm);       acc2 = add2(acc2, u);
        u = mul2(u, cm);       acc3 = add2(acc3, u);
        u = mul2(u, cm);       acc4 = add2(acc4, u);
        a0 += mk;

        float lvl, lvh; up2(lv, lvl, lvh);
        atex = fmaf(fabsf(lvh - lvl), mk, atex);
        float lpl, lph; up2(lap, lpl, lph);
        ashp = fmaf(fabsf(lph - lpl), mk, ashp);

        // roll
        rs0 = rs1; rq0 = rq1; M0 = M1;
        L1 = L2; M1 = M2; R1 = R2; rs1 = rs2; rq1 = rq2;
    }

    float ai1, ao1, ai2, ao2, ai3, ao3, ai4, ao4;
    up2(acc1, ai1, ao1); up2(acc2, ai2, ao2);
    up2(acc3, ai3, ao3); up2(acc4, ai4, ao4);

    // ---- block reduction ----
    WRED(a0);
    WRED(ai1); WRED(ai2); WRED(ai3); WRED(ai4);
    WRED(ao1); WRED(ao2); WRED(ao3); WRED(ao4);
    WRED(atex); WRED(ashp);

    int warp = tid >> 5, lane = tid & 31;
    if (lane == 0) {
        red[warp][0] = (double)a0;
        red[warp][1] = (double)ai1; red[warp][2] = (double)ai2;
        red[warp][3] = (double)ai3; red[warp][4] = (double)ai4;
        red[warp][5] = (double)ao1; red[warp][6] = (double)ao2;
        red[warp][7] = (double)ao3; red[warp][8] = (double)ao4;
        red[warp][9] = (double)atex; red[warp][10] = (double)ashp;
    }
    __syncthreads();
    if (tid < 11) {
        double s = 0.0;
#pragma unroll
        for (int w = 0; w < 8; w++) s += red[w][tid];
        atomicAdd(&g_acc[tid], s);
    }

    // ---- last block finalizes + resets state (graph-replay determinism) ----
    if (tid == 0) {
        __threadfence();
        unsigned int old = atomicAdd(&g_count, 1u);
        last_flag = (old == (unsigned)(NBLOCKS - 1));
    }
    __syncthreads();
    if (!last_flag) return;

    if (tid == 0) {
        double v[11];
#pragma unroll
        for (int i = 0; i < 11; i++) v[i] = atomicAdd(&g_acc[i], 0.0);  // L2-coherent read

        const double EPS = 1e-8;
        double S0 = v[0];
        double A1 = v[1], A2 = v[2], A3 = v[3], A4 = v[4];
        double B1 = v[5], B2 = v[6], B3 = v[7], B4 = v[8];

        double ms = S0 + EPS;
        double im = A1 / ms, om = B1 / ms;
        double im2 = im * im, im3 = im2 * im, im4 = im2 * im2;
        double om2 = om * om, om3 = om2 * om, om4 = om2 * om2;

        double di2 = A2 - 2.0 * im * A1 + im2 * S0;
        double di3 = A3 - 3.0 * im * A2 + 3.0 * im2 * A1 - im3 * S0;
        double di4 = A4 - 4.0 * im * A3 + 6.0 * im2 * A2 - 4.0 * im3 * A1 + im4 * S0;
        double do2 = B2 - 2.0 * om * B1 + om2 * S0;
        double do3 = B3 - 3.0 * om * B2 + 3.0 * om2 * B1 - om3 * S0;
        double do4 = B4 - 4.0 * om * B3 + 6.0 * om2 * B2 - 4.0 * om3 * B1 + om4 * S0;

        double iv = di2 / ms, ov = do2 / ms;
        double isk = di3 / (ms * (iv * sqrt(iv) + EPS));
        double osk = do3 / (ms * (ov * sqrt(ov) + EPS));
        double iku = di4 / (ms * (iv * iv + EPS));
        double oku = do4 / (ms * (ov * ov + EPS));

        double dm = im - om, dv = iv - ov, dsk = isk - osk, dku = iku - oku;
        double intensity = dm * dm + dv * dv + dsk * dsk + dku * dku;

        const double NTOT = (double)Bimg * (double)Himg * (double)Wimg;
        double texture = v[9] / NTOT;
        double shapev = v[10] / NTOT;
        double total = intensity + texture + 0.5 * shapev;

        out[0] = (float)intensity;
        out[1] = (float)texture;
        out[2] = (float)shapev;
        out[3] = (float)total;

        // reset for next (graph-replayed) launch
#pragma unroll
        for (int i = 0; i < 11; i++)
            atomicExch((unsigned long long*)&g_acc[i], 0ull);
        __threadfence();
        atomicExch(&g_count, 0u);
    }
}

extern "C" void kernel_launch(void* const* d_in, const int* in_sizes, int n_in,
                              void* d_out, int out_size) {
    (void)in_sizes; (void)n_in; (void)out_size;
    const float* inp  = (const float*)d_in[0];
    const float* outp = (const float*)d_in[1];
    const float* mask = (const float*)d_in[2];

    dim3 grid(Wimg / TILE_W, Himg / TILE_H, Bimg);   // 8 x 16 x 32 = 4096
    dim3 block(TILE_W, TILE_H / ROWS);               // 64 x 4 = 256
    loss_kernel<<<grid, block>>>(inp, outp, mask, (float*)d_out);
}

// round 5
// speedup vs baseline: 1.8390x; 1.8390x over previous
#include <cuda_runtime.h>
#include <math.h>

namespace {
constexpr int Himg = 512, Wimg = 512, Bimg = 32;
constexpr int WARPS = 4;                 // warps per block
constexpr int ROWS  = 8;                 // rows per warp strip
constexpr int BLK_ROWS = WARPS * ROWS;   // 32 rows per block
constexpr int GX = Wimg / 128;           // 4 warp-column strips
constexpr int GY = Himg / BLK_ROWS;      // 16
constexpr int NBLOCKS = GX * GY * Bimg;  // 2048
}

// [0]=mask sum, [1..4]=inp S1..S4, [5..8]=out S1..S4, [9]=tex, [10]=shape
__device__ double g_acc[11];
__device__ unsigned int g_count;

struct HR { float4 hs, hq, v; };

// Load one image row segment (4 cols/lane) and build horizontal 3-tap sums.
__device__ __forceinline__ HR hrow(const float* __restrict__ img, long rowoff, bool rowok,
                                   int c0, int lane, bool has_l, bool has_r) {
    HR h;
    float4 v;
    if (rowok) v = *(const float4*)(img + rowoff + c0);
    else       v = make_float4(0.f, 0.f, 0.f, 0.f);
    float vl = __shfl_up_sync(0xffffffffu, v.w, 1);
    float vr = __shfl_down_sync(0xffffffffu, v.x, 1);
    if (lane == 0)  vl = (rowok && has_l) ? img[rowoff + c0 - 1] : 0.f;
    if (lane == 31) vr = (rowok && has_r) ? img[rowoff + c0 + 4] : 0.f;

    float s01 = v.x + v.y, s23 = v.z + v.w;
    h.hs.x = vl + s01;
    h.hs.y = s01 + v.z;
    h.hs.z = v.y + s23;
    h.hs.w = s23 + vr;
    float qx = v.x * v.x, qy = v.y * v.y, qz = v.z * v.z, qw = v.w * v.w;
    float ql = vl * vl, qr = vr * vr;
    float q01 = qx + qy, q23 = qz + qw;
    h.hq.x = ql + q01;
    h.hq.y = q01 + qz;
    h.hq.z = qy + q23;
    h.hq.w = q23 + qr;
    h.v = v;
    return h;
}

#define WRED(v)                                      \
    v += __shfl_xor_sync(0xffffffffu, v, 16);        \
    v += __shfl_xor_sync(0xffffffffu, v, 8);         \
    v += __shfl_xor_sync(0xffffffffu, v, 4);         \
    v += __shfl_xor_sync(0xffffffffu, v, 2);         \
    v += __shfl_xor_sync(0xffffffffu, v, 1);

__global__ __launch_bounds__(128) void loss_kernel(
    const float* __restrict__ inp, const float* __restrict__ outp,
    const float* __restrict__ mask, float* __restrict__ out) {
    __shared__ double red[WARPS][11];
    __shared__ int last_flag;

    const int lane = threadIdx.x & 31;
    const int warp = threadIdx.x >> 5;
    const int c0 = blockIdx.x * 128 + lane * 4;
    const int ybase = blockIdx.y * BLK_ROWS + warp * ROWS;
    const size_t ibase = (size_t)blockIdx.z * (size_t)(Himg * Wimg);
    const bool has_l = blockIdx.x > 0;
    const bool has_r = blockIdx.x < GX - 1;
    const float* ib = inp + ibase;
    const float* ob = outp + ibase;
    const float* mb = mask + ibase;

    // ---- prime rolling window (rows ybase-1, ybase) ----
    HR i0 = hrow(ib, (long)(ybase - 1) * Wimg, ybase > 0, c0, lane, has_l, has_r);
    HR o0 = hrow(ob, (long)(ybase - 1) * Wimg, ybase > 0, c0, lane, has_l, has_r);
    HR i1 = hrow(ib, (long)ybase * Wimg, true, c0, lane, has_l, has_r);
    HR o1 = hrow(ob, (long)ybase * Wimg, true, c0, lane, has_l, has_r);

    float a0 = 0.f;
    float ai1 = 0.f, ai2 = 0.f, ai3 = 0.f, ai4 = 0.f;
    float ao1 = 0.f, ao2 = 0.f, ao3 = 0.f, ao4 = 0.f;
    float atex = 0.f, ashp = 0.f;

#pragma unroll
    for (int k = 0; k < ROWS; k++) {
        const int yb = ybase + k;
        HR i2 = hrow(ib, (long)(yb + 1) * Wimg, yb + 1 < Himg, c0, lane, has_l, has_r);
        HR o2 = hrow(ob, (long)(yb + 1) * Wimg, yb + 1 < Himg, c0, lane, has_l, has_r);
        float4 mk4 = *(const float4*)(mb + (size_t)yb * Wimg + c0);

#define COMP(J)                                                            \
        {                                                                  \
            float s1i = i0.hs.J + i1.hs.J + i2.hs.J;                       \
            float s2i = i0.hq.J + i1.hq.J + i2.hq.J;                       \
            float s1o = o0.hs.J + o1.hs.J + o2.hs.J;                       \
            float s2o = o0.hq.J + o1.hq.J + o2.hq.J;                       \
            float ci = i1.v.J, co = o1.v.J;                                \
            float ti = (i0.v.J + i2.v.J) + i1.hs.J;                        \
            float lapi = fmaf(ci, -5.f, ti);                               \
            float to = (o0.v.J + o2.v.J) + o1.hs.J;                        \
            float lapo = fmaf(co, -5.f, to);                               \
            float mi = s1i * (1.f / 9.f), mo_ = s1o * (1.f / 9.f);         \
            float lvi = fmaf(-mi, mi, s2i * (1.f / 9.f));                  \
            float lvo = fmaf(-mo_, mo_, s2o * (1.f / 9.f));                \
            float mk = mk4.J;                                              \
            a0 += mk;                                                      \
            float cim = ci * mk, ci2m = ci * cim;                          \
            float ci3m = ci * ci2m, ci4m = ci * ci3m;                      \
            ai1 += cim; ai2 += ci2m; ai3 += ci3m; ai4 += ci4m;             \
            float com = co * mk, co2m = co * com;                          \
            float co3m = co * co2m, co4m = co * co3m;                      \
            ao1 += com; ao2 += co2m; ao3 += co3m; ao4 += co4m;             \
            atex = fmaf(fabsf(lvo - lvi), mk, atex);                       \
            ashp = fmaf(fabsf(lapo - lapi), mk, ashp);                     \
        }
        COMP(x) COMP(y) COMP(z) COMP(w)
#undef COMP

        i0 = i1; i1 = i2;
        o0 = o1; o1 = o2;
    }

    // ---- reduction: warp shuffle, then cross-warp doubles ----
    WRED(a0);
    WRED(ai1); WRED(ai2); WRED(ai3); WRED(ai4);
    WRED(ao1); WRED(ao2); WRED(ao3); WRED(ao4);
    WRED(atex); WRED(ashp);

    if (lane == 0) {
        red[warp][0] = (double)a0;
        red[warp][1] = (double)ai1; red[warp][2] = (double)ai2;
        red[warp][3] = (double)ai3; red[warp][4] = (double)ai4;
        red[warp][5] = (double)ao1; red[warp][6] = (double)ao2;
        red[warp][7] = (double)ao3; red[warp][8] = (double)ao4;
        red[warp][9] = (double)atex; red[warp][10] = (double)ashp;
    }
    __syncthreads();
    if (threadIdx.x < 11) {
        double s = 0.0;
#pragma unroll
        for (int w = 0; w < WARPS; w++) s += red[w][threadIdx.x];
        atomicAdd(&g_acc[threadIdx.x], s);
    }

    // ---- last block finalizes + resets (graph-replay deterministic) ----
    if (threadIdx.x == 0) {
        __threadfence();
        unsigned int old = atomicAdd(&g_count, 1u);
        last_flag = (old == (unsigned)(NBLOCKS - 1));
    }
    __syncthreads();
    if (!last_flag) return;

    if (threadIdx.x == 0) {
        double v[11];
#pragma unroll
        for (int i = 0; i < 11; i++) v[i] = atomicAdd(&g_acc[i], 0.0);

        const double EPS = 1e-8;
        double S0 = v[0];
        double A1 = v[1], A2 = v[2], A3 = v[3], A4 = v[4];
        double B1 = v[5], B2 = v[6], B3 = v[7], B4 = v[8];

        double ms = S0 + EPS;
        double im = A1 / ms, om = B1 / ms;
        double im2 = im * im, im3 = im2 * im, im4 = im2 * im2;
        double om2 = om * om, om3 = om2 * om, om4 = om2 * om2;

        double di2 = A2 - 2.0 * im * A1 + im2 * S0;
        double di3 = A3 - 3.0 * im * A2 + 3.0 * im2 * A1 - im3 * S0;
        double di4 = A4 - 4.0 * im * A3 + 6.0 * im2 * A2 - 4.0 * im3 * A1 + im4 * S0;
        double do2 = B2 - 2.0 * om * B1 + om2 * S0;
        double do3 = B3 - 3.0 * om * B2 + 3.0 * om2 * B1 - om3 * S0;
        double do4 = B4 - 4.0 * om * B3 + 6.0 * om2 * B2 - 4.0 * om3 * B1 + om4 * S0;

        double iv = di2 / ms, ov = do2 / ms;
        double isk = di3 / (ms * (iv * sqrt(iv) + EPS));
        double osk = do3 / (ms * (ov * sqrt(ov) + EPS));
        double iku = di4 / (ms * (iv * iv + EPS));
        double oku = do4 / (ms * (ov * ov + EPS));

        double dm = im - om, dv = iv - ov, dsk = isk - osk, dku = iku - oku;
        double intensity = dm * dm + dv * dv + dsk * dsk + dku * dku;

        const double NTOT = (double)Bimg * (double)Himg * (double)Wimg;
        double texture = v[9] / NTOT;
        double shapev = v[10] / NTOT;
        double total = intensity + texture + 0.5 * shapev;

        out[0] = (float)intensity;
        out[1] = (float)texture;
        out[2] = (float)shapev;
        out[3] = (float)total;

#pragma unroll
        for (int i = 0; i < 11; i++)
            atomicExch((unsigned long long*)&g_acc[i], 0ull);
        __threadfence();
        atomicExch(&g_count, 0u);
    }
}

extern "C" void kernel_launch(void* const* d_in, const int* in_sizes, int n_in,
                              void* d_out, int out_size) {
    (void)in_sizes; (void)n_in; (void)out_size;
    const float* inp  = (const float*)d_in[0];
    const float* outp = (const float*)d_in[1];
    const float* mask = (const float*)d_in[2];

    dim3 grid(GX, GY, Bimg);   // 4 x 16 x 32 = 2048
    dim3 block(128);
    loss_kernel<<<grid, block>>>(inp, outp, mask, (float*)d_out);
}

// round 6
// speedup vs baseline: 2.0133x; 1.0948x over previous
#include <cuda_runtime.h>
#include <math.h>

namespace {
constexpr int Himg = 512, Wimg = 512, Bimg = 32;
constexpr int WARPS = 4;                 // warps per block (stacked vertically)
constexpr int ROWS  = 16;                // rows per warp strip
constexpr int BLK_ROWS = WARPS * ROWS;   // 64 rows per block
constexpr int GX = Wimg / 64;            // 8 warp-column strips (64 cols each)
constexpr int GY = Himg / BLK_ROWS;      // 8
constexpr int NBLOCKS = GX * GY * Bimg;  // 2048
}

// [0]=mask sum, [1..4]=inp S1..S4, [5..8]=out S1..S4, [9]=tex, [10]=shape
__device__ double g_acc[11];
__device__ unsigned int g_count;

struct HR2 { float hs0, hs1, hq0, hq1, v0, v1; };

// Load 2 cols/lane of one image row; build horizontal 3-tap sum / sq-sum.
__device__ __forceinline__ HR2 hrow2(const float* __restrict__ img, long rowoff, bool rowok,
                                     int c0, int lane, bool has_l, bool has_r) {
    HR2 h;
    float2 v;
    if (rowok) v = *(const float2*)(img + rowoff + c0);
    else       v = make_float2(0.f, 0.f);
    float vl = __shfl_up_sync(0xffffffffu, v.y, 1);
    float vr = __shfl_down_sync(0xffffffffu, v.x, 1);
    if (lane == 0)  vl = (rowok && has_l) ? img[rowoff + c0 - 1] : 0.f;
    if (lane == 31) vr = (rowok && has_r) ? img[rowoff + c0 + 2] : 0.f;

    float s = v.x + v.y;
    float q = fmaf(v.x, v.x, v.y * v.y);
    h.hs0 = vl + s;
    h.hs1 = s + vr;
    h.hq0 = fmaf(vl, vl, q);
    h.hq1 = fmaf(vr, vr, q);
    h.v0 = v.x; h.v1 = v.y;
    return h;
}

#define WRED(v)                                      \
    v += __shfl_xor_sync(0xffffffffu, v, 16);        \
    v += __shfl_xor_sync(0xffffffffu, v, 8);         \
    v += __shfl_xor_sync(0xffffffffu, v, 4);         \
    v += __shfl_xor_sync(0xffffffffu, v, 2);         \
    v += __shfl_xor_sync(0xffffffffu, v, 1);

__global__ __launch_bounds__(128) void loss_kernel(
    const float* __restrict__ inp, const float* __restrict__ outp,
    const float* __restrict__ mask, float* __restrict__ out) {
    __shared__ double red[WARPS][11];
    __shared__ int last_flag;

    const int lane = threadIdx.x & 31;
    const int warp = threadIdx.x >> 5;
    const int c0 = blockIdx.x * 64 + lane * 2;
    const int ybase = blockIdx.y * BLK_ROWS + warp * ROWS;
    const size_t ibase = (size_t)blockIdx.z * (size_t)(Himg * Wimg);
    const bool has_l = blockIdx.x > 0;
    const bool has_r = blockIdx.x < GX - 1;
    const float* ib = inp + ibase;
    const float* ob = outp + ibase;
    const float* mb = mask + ibase;

    // ---- prime rolling window (rows ybase-1, ybase) ----
    HR2 i0 = hrow2(ib, (long)(ybase - 1) * Wimg, ybase > 0, c0, lane, has_l, has_r);
    HR2 o0 = hrow2(ob, (long)(ybase - 1) * Wimg, ybase > 0, c0, lane, has_l, has_r);
    HR2 i1 = hrow2(ib, (long)ybase * Wimg, true, c0, lane, has_l, has_r);
    HR2 o1 = hrow2(ob, (long)ybase * Wimg, true, c0, lane, has_l, has_r);

    float a0 = 0.f;
    float ai1 = 0.f, ai2 = 0.f, ai3 = 0.f, ai4 = 0.f;
    float ao1 = 0.f, ao2 = 0.f, ao3 = 0.f, ao4 = 0.f;
    float atex = 0.f, ashp = 0.f;

#pragma unroll
    for (int k = 0; k < ROWS; k++) {
        const int yb = ybase + k;
        HR2 i2 = hrow2(ib, (long)(yb + 1) * Wimg, yb + 1 < Himg, c0, lane, has_l, has_r);
        HR2 o2 = hrow2(ob, (long)(yb + 1) * Wimg, yb + 1 < Himg, c0, lane, has_l, has_r);
        float2 mk2 = *(const float2*)(mb + (size_t)yb * Wimg + c0);

#define COMP(HS, HQ, V, MK)                                                \
        {                                                                  \
            float s1i = i0.HS + i1.HS + i2.HS;                             \
            float s2i = i0.HQ + i1.HQ + i2.HQ;                             \
            float s1o = o0.HS + o1.HS + o2.HS;                             \
            float s2o = o0.HQ + o1.HQ + o2.HQ;                             \
            float ci = i1.V, co = o1.V;                                    \
            float ti = (i0.V + i2.V) + i1.HS;                              \
            float lapi = fmaf(ci, -5.f, ti);                               \
            float to = (o0.V + o2.V) + o1.HS;                              \
            float lapo = fmaf(co, -5.f, to);                               \
            float mi = s1i * (1.f / 9.f), mo_ = s1o * (1.f / 9.f);         \
            float lvi = fmaf(-mi, mi, s2i * (1.f / 9.f));                  \
            float lvo = fmaf(-mo_, mo_, s2o * (1.f / 9.f));                \
            float mk = MK;                                                 \
            a0 += mk;                                                      \
            float cim = ci * mk, ci2m = ci * cim;                          \
            float ci3m = ci * ci2m, ci4m = ci * ci3m;                      \
            ai1 += cim; ai2 += ci2m; ai3 += ci3m; ai4 += ci4m;             \
            float com = co * mk, co2m = co * com;                          \
            float co3m = co * co2m, co4m = co * co3m;                      \
            ao1 += com; ao2 += co2m; ao3 += co3m; ao4 += co4m;             \
            atex = fmaf(fabsf(lvo - lvi), mk, atex);                       \
            ashp = fmaf(fabsf(lapo - lapi), mk, ashp);                     \
        }
        COMP(hs0, hq0, v0, mk2.x)
        COMP(hs1, hq1, v1, mk2.y)
#undef COMP

        i0 = i1; i1 = i2;
        o0 = o1; o1 = o2;
    }

    // ---- reduction: warp shuffle, then cross-warp doubles ----
    WRED(a0);
    WRED(ai1); WRED(ai2); WRED(ai3); WRED(ai4);
    WRED(ao1); WRED(ao2); WRED(ao3); WRED(ao4);
    WRED(atex); WRED(ashp);

    if (lane == 0) {
        red[warp][0] = (double)a0;
        red[warp][1] = (double)ai1; red[warp][2] = (double)ai2;
        red[warp][3] = (double)ai3; red[warp][4] = (double)ai4;
        red[warp][5] = (double)ao1; red[warp][6] = (double)ao2;
        red[warp][7] = (double)ao3; red[warp][8] = (double)ao4;
        red[warp][9] = (double)atex; red[warp][10] = (double)ashp;
    }
    __syncthreads();
    if (threadIdx.x < 11) {
        double s = 0.0;
#pragma unroll
        for (int w = 0; w < WARPS; w++) s += red[w][threadIdx.x];
        atomicAdd(&g_acc[threadIdx.x], s);
    }

    // ---- last block finalizes + resets (graph-replay deterministic) ----
    if (threadIdx.x == 0) {
        __threadfence();
        unsigned int old = atomicAdd(&g_count, 1u);
        last_flag = (old == (unsigned)(NBLOCKS - 1));
    }
    __syncthreads();
    if (!last_flag) return;

    if (threadIdx.x == 0) {
        double v[11];
#pragma unroll
        for (int i = 0; i < 11; i++) v[i] = atomicAdd(&g_acc[i], 0.0);

        const double EPS = 1e-8;
        double S0 = v[0];
        double A1 = v[1], A2 = v[2], A3 = v[3], A4 = v[4];
        double B1 = v[5], B2 = v[6], B3 = v[7], B4 = v[8];

        double ms = S0 + EPS;
        double im = A1 / ms, om = B1 / ms;
        double im2 = im * im, im3 = im2 * im, im4 = im2 * im2;
        double om2 = om * om, om3 = om2 * om, om4 = om2 * om2;

        double di2 = A2 - 2.0 * im * A1 + im2 * S0;
        double di3 = A3 - 3.0 * im * A2 + 3.0 * im2 * A1 - im3 * S0;
        double di4 = A4 - 4.0 * im * A3 + 6.0 * im2 * A2 - 4.0 * im3 * A1 + im4 * S0;
        double do2 = B2 - 2.0 * om * B1 + om2 * S0;
        double do3 = B3 - 3.0 * om * B2 + 3.0 * om2 * B1 - om3 * S0;
        double do4 = B4 - 4.0 * om * B3 + 6.0 * om2 * B2 - 4.0 * om3 * B1 + om4 * S0;

        double iv = di2 / ms, ov = do2 / ms;
        double isk = di3 / (ms * (iv * sqrt(iv) + EPS));
        double osk = do3 / (ms * (ov * sqrt(ov) + EPS));
        double iku = di4 / (ms * (iv * iv + EPS));
        double oku = do4 / (ms * (ov * ov + EPS));

        double dm = im - om, dv = iv - ov, dsk = isk - osk, dku = iku - oku;
        double intensity = dm * dm + dv * dv + dsk * dsk + dku * dku;

        const double NTOT = (double)Bimg * (double)Himg * (double)Wimg;
        double texture = v[9] / NTOT;
        double shapev = v[10] / NTOT;
        double total = intensity + texture + 0.5 * shapev;

        out[0] = (float)intensity;
        out[1] = (float)texture;
        out[2] = (float)shapev;
        out[3] = (float)total;

#pragma unroll
        for (int i = 0; i < 11; i++)
            atomicExch((unsigned long long*)&g_acc[i], 0ull);
        __threadfence();
        atomicExch(&g_count, 0u);
    }
}

extern "C" void kernel_launch(void* const* d_in, const int* in_sizes, int n_in,
                              void* d_out, int out_size) {
    (void)in_sizes; (void)n_in; (void)out_size;
    const float* inp  = (const float*)d_in[0];
    const float* outp = (const float*)d_in[1];
    const float* mask = (const float*)d_in[2];

    dim3 grid(GX, GY, Bimg);   // 8 x 8 x 32 = 2048
    dim3 block(128);
    loss_kernel<<<grid, block>>>(inp, outp, mask, (float*)d_out);
}